// round 13
// baseline (speedup 1.0000x reference)
#include <cuda_runtime.h>
#include <cstdint>

// TopK-magnitude masking per row. x: (4096, 8192) fp32, K = 819.
// out[r,c] = x[r,c] if |x[r,c]| >= (K-th largest |x| in row r) else 0.
//
// Bracketed exact select: rows are N(0,1), so the 819th largest |x| lies in
// [1.5, 1.8] with ~9-sigma margin. One fused global sweep writes the final
// output for all decided elements (|x|<1.5 -> 0, |x|>1.8 -> keep), counts the
// ">1.8" population, and collects the ~500 bracket elements into smem. An
// EXACT 2-pass radix select over those candidates yields the true K-th key;
// a tiny scattered fixup zeroes bracket losers. If the bracket assumption
// fails (CTA-uniform check), a full 3-pass radix fallback re-reads x from
// global and recomputes everything exactly -- correct for ANY input.

#define ROWLEN  8192
#define TPB     512
#define KSEL    819u
#define NW      (TPB / 32)     // 16 warps
#define CANDMAX 1024
#define KA      0x3FC00000u    // bits(1.5f)
#define KB      0x3FE66666u    // bits(1.8f)

// Suffix-scan + digit select over h[NB] (B = NB/TPB bins per thread).
// Outputs *sh_digit, *sh_k (rank within digit). Ends with __syncthreads.
template <int NB>
__device__ __forceinline__ void suffix_select(
    const unsigned* __restrict__ h, unsigned k,
    int t, int lane, int wid,
    unsigned* wsum, unsigned* wtail,
    unsigned* sh_digit, unsigned* sh_k)
{
    constexpr int B = NB / TPB;
    const int base = t * B;
    unsigned loc[B];
    unsigned s = 0u;
#pragma unroll
    for (int j = B - 1; j >= 0; j--) { s += h[base + j]; loc[j] = s; }
    unsigned p = s;                        // warp suffix scan of chunk totals
#pragma unroll
    for (int off = 1; off < 32; off <<= 1) {
        unsigned n = __shfl_down_sync(0xFFFFFFFFu, p, off);
        if (lane < 32 - off) p += n;
    }
    if (lane == 0) wsum[wid] = p;
    __syncthreads();
    if (t < NW) {
        unsigned q = wsum[t];
        unsigned r = q;
#pragma unroll
        for (int off = 1; off < NW; off <<= 1) {
            unsigned n = __shfl_down_sync(0x0000FFFFu, r, off);
            if (t < NW - off) r += n;
        }
        wtail[t] = r - q;                  // total of warps AFTER warp t
    }
    __syncthreads();
    unsigned beyond = (p - s) + wtail[wid];
#pragma unroll
    for (int j = 0; j < B; j++) {
        unsigned incl = loc[j] + beyond;                          // count(>=d)
        unsigned cnt  = loc[j] - ((j < B - 1) ? loc[j + 1] : 0u); // hist[d]
        unsigned gt   = incl - cnt;                               // count(>d)
        if (incl >= k && gt < k) { *sh_digit = (unsigned)(base + j); *sh_k = k - gt; }
    }
    __syncthreads();
}

__global__ __launch_bounds__(TPB, 4)
void topk_mask_kernel(const float* __restrict__ x, float* __restrict__ out) {
    __shared__ unsigned       hist[2048];        // 8 KB
    __shared__ unsigned       ck[CANDMAX];       // 4 KB  candidate keys
    __shared__ unsigned short cpos[CANDMAX];     // 2 KB  candidate positions
    __shared__ unsigned       wsum[NW], wtail[NW];
    __shared__ unsigned       sh_digit, sh_k, hicnt, ccnt;

    const int t    = threadIdx.x;
    const int lane = t & 31;
    const int wid  = t >> 5;
    const size_t row_off = (size_t)blockIdx.x * ROWLEN;
    const uint4* __restrict__ px   = reinterpret_cast<const uint4*>(x + row_off);
    uint4*       __restrict__ po   = reinterpret_cast<uint4*>(out + row_off);
    float*       __restrict__ pout = out + row_off;

    // ---- init ----
    reinterpret_cast<uint4*>(hist)[t] = make_uint4(0u, 0u, 0u, 0u);
    if (t == 0) { hicnt = 0u; ccnt = 0u; }
    __syncthreads();

    // ---- fused sweep: load -> final store of decided elems + hi-count +
    //      bracket-candidate collection ----
    unsigned myhi = 0u;
#pragma unroll
    for (int i = 0; i < 4; i++) {
        uint4 a = px[t + i * TPB];
        const unsigned b[4] = {a.x, a.y, a.z, a.w};
        unsigned o[4];
#pragma unroll
        for (int c = 0; c < 4; c++) {
            unsigned key = b[c] & 0x7FFFFFFFu;
            // |x|<1.5 -> 0; |x|>1.8 -> keep; bracket -> provisional keep
            o[c] = (key < KA) ? 0u : b[c];
            myhi += (key > KB);
            if (key >= KA && key <= KB) {
                unsigned idx = atomicAdd(&ccnt, 1u);
                if (idx < CANDMAX) {
                    ck[idx]   = key;
                    cpos[idx] = (unsigned short)(4 * (t + i * TPB) + c);
                }
            }
        }
        po[t + i * TPB] = make_uint4(o[0], o[1], o[2], o[3]);
    }
    // warp-reduce hi count, one atomic per warp
#pragma unroll
    for (int off = 16; off >= 1; off >>= 1)
        myhi += __shfl_down_sync(0xFFFFFFFFu, myhi, off);
    if (lane == 0) atomicAdd(&hicnt, myhi);
    __syncthreads();

    const unsigned HI = hicnt;
    const unsigned CC = ccnt;
    const bool fast = (HI < KSEL) && (CC <= CANDMAX) && (HI + CC >= KSEL);

    if (fast) {
        unsigned k = KSEL - HI;            // rank of threshold among candidates

        // ---- pass A: mantissa bits [11,22), 2048 bins, ~1 cand/thread ----
        for (unsigned j = t; j < CC; j += TPB)
            atomicAdd(&hist[(ck[j] >> 11) & 0x7FFu], 1u);
        __syncthreads();
        suffix_select<2048>(hist, k, t, lane, wid, wsum, wtail, &sh_digit, &sh_k);
        const unsigned dA = sh_digit; k = sh_k;

        // ---- pass B: mantissa bits [0,11), 2048 bins ----
        reinterpret_cast<uint4*>(hist)[t] = make_uint4(0u, 0u, 0u, 0u);
        __syncthreads();
        for (unsigned j = t; j < CC; j += TPB) {
            unsigned kk = ck[j];
            if (((kk >> 11) & 0x7FFu) == dA)
                atomicAdd(&hist[kk & 0x7FFu], 1u);
        }
        __syncthreads();
        suffix_select<2048>(hist, k, t, lane, wid, wsum, wtail, &sh_digit, &sh_k);

        // all candidates share top bits (key>>22 == KA>>22): exact threshold
        const unsigned T = (KA & 0xFFC00000u) | (dA << 11) | sh_digit;

        // ---- fixup: zero bracket losers (scattered ~250 stores/row) ----
        for (unsigned j = t; j < CC; j += TPB)
            if (ck[j] < T)
                pout[cpos[j]] = 0.0f;
    } else {
        // ======== fallback: exact full 3-pass radix (11+10+10), re-reading
        // x from global. CTA-uniform, never taken for Gaussian rows. ========
        unsigned k = KSEL;

        reinterpret_cast<uint4*>(hist)[t] = make_uint4(0u, 0u, 0u, 0u);
        __syncthreads();
#pragma unroll
        for (int i = 0; i < 4; i++) {
            uint4 a = px[t + i * TPB];
            const unsigned b[4] = {a.x, a.y, a.z, a.w};
#pragma unroll
            for (int c = 0; c < 4; c++)
                atomicAdd(&hist[(b[c] & 0x7FFFFFFFu) >> 20], 1u);
        }
        __syncthreads();
        suffix_select<2048>(hist, k, t, lane, wid, wsum, wtail, &sh_digit, &sh_k);
        const unsigned d1 = sh_digit; k = sh_k;

        reinterpret_cast<uint4*>(hist)[t] = make_uint4(0u, 0u, 0u, 0u);
        __syncthreads();
#pragma unroll
        for (int i = 0; i < 4; i++) {
            uint4 a = px[t + i * TPB];
            const unsigned b[4] = {a.x, a.y, a.z, a.w};
#pragma unroll
            for (int c = 0; c < 4; c++) {
                unsigned kk = b[c] & 0x7FFFFFFFu;
                if ((kk >> 20) == d1)
                    atomicAdd(&hist[(kk >> 10) & 0x3FFu], 1u);
            }
        }
        __syncthreads();
        suffix_select<1024>(hist, k, t, lane, wid, wsum, wtail, &sh_digit, &sh_k);
        const unsigned d2 = sh_digit; k = sh_k;
        const unsigned pref21 = (d1 << 10) | d2;

        reinterpret_cast<uint4*>(hist)[t] = make_uint4(0u, 0u, 0u, 0u);
        __syncthreads();
#pragma unroll
        for (int i = 0; i < 4; i++) {
            uint4 a = px[t + i * TPB];
            const unsigned b[4] = {a.x, a.y, a.z, a.w};
#pragma unroll
            for (int c = 0; c < 4; c++) {
                unsigned kk = b[c] & 0x7FFFFFFFu;
                if ((kk >> 10) == pref21)
                    atomicAdd(&hist[kk & 0x3FFu], 1u);
            }
        }
        __syncthreads();
        suffix_select<1024>(hist, k, t, lane, wid, wsum, wtail, &sh_digit, &sh_k);
        const unsigned T = (pref21 << 10) | sh_digit;

        // full re-store with exact mask
#pragma unroll
        for (int i = 0; i < 4; i++) {
            uint4 a = px[t + i * TPB];
            const unsigned b[4] = {a.x, a.y, a.z, a.w};
            unsigned o[4];
#pragma unroll
            for (int c = 0; c < 4; c++) {
                unsigned kk = b[c] & 0x7FFFFFFFu;
                o[c] = (kk < T) ? 0u : b[c];
            }
            po[t + i * TPB] = make_uint4(o[0], o[1], o[2], o[3]);
        }
    }
}

extern "C" void kernel_launch(void* const* d_in, const int* in_sizes, int n_in,
                              void* d_out, int out_size) {
    const float* x = (const float*)d_in[0];
    float* out = (float*)d_out;
    const int rows = in_sizes[0] / ROWLEN;   // 4096
    topk_mask_kernel<<<rows, TPB>>>(x, out);
}

// round 14
// speedup vs baseline: 1.5049x; 1.5049x over previous
#include <cuda_runtime.h>
#include <cstdint>

// TopK-magnitude masking per row. x: (4096, 8192) fp32, K = 819.
// out[r,c] = x[r,c] if |x[r,c]| >= (K-th largest |x| in row r) else 0.
//
// Bracketed exact select. Rows are N(0,1): the 819th largest |x| lies in
// [1.5, 1.8] with ~9-sigma margins. ONE fused global sweep writes the final
// output for decided elements (|x|<1.5 -> 0, else keep provisionally),
// accumulating a per-thread candidacy bitmask and a ">1.8" count in pure
// registers (NO atomics, NO ballots in the sweep). A single block scan
// assigns compaction offsets; candidates (~505/row) are then written to smem
// and an EXACT 2-pass radix select over them yields the true K-th key; a
// scattered fixup zeroes bracket losers. CTA-uniform fallback to a full
// 3-pass radix (re-reading x) keeps the kernel exact for ANY input.

#define ROWLEN  8192
#define TPB     512
#define KSEL    819u
#define NW      (TPB / 32)     // 16 warps
#define CANDMAX 1024
#define KA      0x3FC00000u    // bits(1.5f)
#define KB      0x3FE66666u    // bits(1.8f)

// Suffix-scan + digit select over h[NB] (B = NB/TPB bins per thread).
// Outputs *sh_digit, *sh_k (rank within digit). Ends with __syncthreads.
template <int NB>
__device__ __forceinline__ void suffix_select(
    const unsigned* __restrict__ h, unsigned k,
    int t, int lane, int wid,
    unsigned* wsum, unsigned* wtail,
    unsigned* sh_digit, unsigned* sh_k)
{
    constexpr int B = NB / TPB;
    const int base = t * B;
    unsigned loc[B];
    unsigned s = 0u;
#pragma unroll
    for (int j = B - 1; j >= 0; j--) { s += h[base + j]; loc[j] = s; }
    unsigned p = s;                        // warp suffix scan of chunk totals
#pragma unroll
    for (int off = 1; off < 32; off <<= 1) {
        unsigned n = __shfl_down_sync(0xFFFFFFFFu, p, off);
        if (lane < 32 - off) p += n;
    }
    if (lane == 0) wsum[wid] = p;
    __syncthreads();
    if (t < NW) {
        unsigned q = wsum[t];
        unsigned r = q;
#pragma unroll
        for (int off = 1; off < NW; off <<= 1) {
            unsigned n = __shfl_down_sync(0x0000FFFFu, r, off);
            if (t < NW - off) r += n;
        }
        wtail[t] = r - q;                  // total of warps AFTER warp t
    }
    __syncthreads();
    unsigned beyond = (p - s) + wtail[wid];
#pragma unroll
    for (int j = 0; j < B; j++) {
        unsigned incl = loc[j] + beyond;                          // count(>=d)
        unsigned cnt  = loc[j] - ((j < B - 1) ? loc[j + 1] : 0u); // hist[d]
        unsigned gt   = incl - cnt;                               // count(>d)
        if (incl >= k && gt < k) { *sh_digit = (unsigned)(base + j); *sh_k = k - gt; }
    }
    __syncthreads();
}

__global__ __launch_bounds__(TPB, 4)
void topk_mask_kernel(const float* __restrict__ x, float* __restrict__ out) {
    __shared__ unsigned       hist[2048];        // 8 KB
    __shared__ unsigned       ck[CANDMAX];       // 4 KB  candidate keys
    __shared__ unsigned short cpos[CANDMAX];     // 2 KB  candidate positions
    __shared__ unsigned       wsum[NW], wtail[NW], whi[NW], wbase[NW];
    __shared__ unsigned       sh_digit, sh_k, sh_cc, sh_hi;

    const int t    = threadIdx.x;
    const int lane = t & 31;
    const int wid  = t >> 5;
    const size_t row_off = (size_t)blockIdx.x * ROWLEN;
    const unsigned* __restrict__ pxs = reinterpret_cast<const unsigned*>(x + row_off);
    const uint4*    __restrict__ px  = reinterpret_cast<const uint4*>(x + row_off);
    uint4*          __restrict__ po  = reinterpret_cast<uint4*>(out + row_off);
    float*          __restrict__ pout = out + row_off;

    // ---- zero pass-A histogram ----
    reinterpret_cast<uint4*>(hist)[t] = make_uint4(0u, 0u, 0u, 0u);
    __syncthreads();

    // ---- fused sweep: load -> final store + register-only bookkeeping ----
    unsigned cmask = 0u;     // bit idx=i*4+c set if element is a candidate
    unsigned myhi  = 0u;     // count of |x| > 1.8
#pragma unroll
    for (int i = 0; i < 4; i++) {
        uint4 a = px[t + i * TPB];
        const unsigned b[4] = {a.x, a.y, a.z, a.w};
        unsigned o[4];
#pragma unroll
        for (int c = 0; c < 4; c++) {
            unsigned key = b[c] & 0x7FFFFFFFu;
            o[c] = (key < KA) ? 0u : b[c];           // decided or provisional
            myhi += (key > KB);
            cmask |= (unsigned)(key >= KA && key <= KB) << (i * 4 + c);
        }
        po[t + i * TPB] = make_uint4(o[0], o[1], o[2], o[3]);
    }
    const unsigned cnt = (unsigned)__popc(cmask);

    // ---- block scan of candidate counts + block reduce of hi counts ----
    {
        unsigned inc = cnt;                 // warp inclusive scan
#pragma unroll
        for (int off = 1; off < 32; off <<= 1) {
            unsigned n = __shfl_up_sync(0xFFFFFFFFu, inc, off);
            if (lane >= off) inc += n;
        }
        unsigned h = myhi;                  // warp reduce
#pragma unroll
        for (int off = 16; off >= 1; off >>= 1)
            h += __shfl_down_sync(0xFFFFFFFFu, h, off);
        if (lane == 31) wsum[wid] = inc;
        if (lane == 0)  whi[wid]  = h;
        __syncthreads();
        if (t < NW) {
            unsigned q = wsum[t];
            unsigned e = q;                 // inclusive scan over 16 warps
#pragma unroll
            for (int off = 1; off < NW; off <<= 1) {
                unsigned n = __shfl_up_sync(0x0000FFFFu, e, off);
                if (t >= off) e += n;
            }
            wbase[t] = e - q;               // exclusive base for warp t
            if (t == NW - 1) sh_cc = e;     // total candidates
            unsigned hh = whi[t];
#pragma unroll
            for (int off = NW / 2; off >= 1; off >>= 1)
                hh += __shfl_down_sync(0x0000FFFFu, hh, off);
            if (t == 0) sh_hi = hh;
        }
        __syncthreads();
        // write my candidates (re-read own elements; L2-hot)
        if (sh_cc <= CANDMAX) {
            unsigned off = wbase[wid] + (__shfl_up_sync(0xFFFFFFFFu, inc, 1) & 
                           (lane ? 0xFFFFFFFFu : 0u));   // exclusive within warp
            off = wbase[wid];
            {   // recompute exclusive prefix = inc - cnt
                off += inc - cnt;
            }
#pragma unroll
            for (int idx = 0; idx < 16; idx++) {
                if ((cmask >> idx) & 1u) {
                    const int i = idx >> 2, c = idx & 3;
                    const int pos = 4 * (t + i * TPB) + c;
                    ck[off]   = pxs[pos] & 0x7FFFFFFFu;
                    cpos[off] = (unsigned short)pos;
                    off++;
                }
            }
        }
    }
    __syncthreads();

    const unsigned HI = sh_hi;
    const unsigned CC = sh_cc;
    const bool fast = (HI < KSEL) && (CC <= CANDMAX) && (HI + CC >= KSEL);

    if (fast) {
        unsigned k = KSEL - HI;            // rank among candidates

        // ---- pass A: mantissa bits [11,22), 2048 bins, ~1 cand/thread ----
        for (unsigned j = t; j < CC; j += TPB)
            atomicAdd(&hist[(ck[j] >> 11) & 0x7FFu], 1u);
        __syncthreads();
        suffix_select<2048>(hist, k, t, lane, wid, wsum, wtail, &sh_digit, &sh_k);
        const unsigned dA = sh_digit; k = sh_k;

        // ---- pass B: mantissa bits [0,11), 2048 bins ----
        reinterpret_cast<uint4*>(hist)[t] = make_uint4(0u, 0u, 0u, 0u);
        __syncthreads();
        for (unsigned j = t; j < CC; j += TPB) {
            unsigned kk = ck[j];
            if (((kk >> 11) & 0x7FFu) == dA)
                atomicAdd(&hist[kk & 0x7FFu], 1u);
        }
        __syncthreads();
        suffix_select<2048>(hist, k, t, lane, wid, wsum, wtail, &sh_digit, &sh_k);

        // all candidates share top 10 bits (exp of [1,2)): exact threshold
        const unsigned T = (KA & 0xFFC00000u) | (dA << 11) | sh_digit;

        // ---- fixup: zero bracket losers (scattered ~250 stores/row) ----
        for (unsigned j = t; j < CC; j += TPB)
            if (ck[j] < T)
                pout[cpos[j]] = 0.0f;
    } else {
        // ======== exact fallback: full 3-pass radix (11+10+10) from x ======
        unsigned k = KSEL;

        reinterpret_cast<uint4*>(hist)[t] = make_uint4(0u, 0u, 0u, 0u);
        __syncthreads();
#pragma unroll
        for (int i = 0; i < 4; i++) {
            uint4 a = px[t + i * TPB];
            const unsigned b[4] = {a.x, a.y, a.z, a.w};
#pragma unroll
            for (int c = 0; c < 4; c++)
                atomicAdd(&hist[(b[c] & 0x7FFFFFFFu) >> 20], 1u);
        }
        __syncthreads();
        suffix_select<2048>(hist, k, t, lane, wid, wsum, wtail, &sh_digit, &sh_k);
        const unsigned d1 = sh_digit; k = sh_k;

        reinterpret_cast<uint4*>(hist)[t] = make_uint4(0u, 0u, 0u, 0u);
        __syncthreads();
#pragma unroll
        for (int i = 0; i < 4; i++) {
            uint4 a = px[t + i * TPB];
            const unsigned b[4] = {a.x, a.y, a.z, a.w};
#pragma unroll
            for (int c = 0; c < 4; c++) {
                unsigned kk = b[c] & 0x7FFFFFFFu;
                if ((kk >> 20) == d1)
                    atomicAdd(&hist[(kk >> 10) & 0x3FFu], 1u);
            }
        }
        __syncthreads();
        suffix_select<1024>(hist, k, t, lane, wid, wsum, wtail, &sh_digit, &sh_k);
        const unsigned d2 = sh_digit; k = sh_k;
        const unsigned pref21 = (d1 << 10) | d2;

        reinterpret_cast<uint4*>(hist)[t] = make_uint4(0u, 0u, 0u, 0u);
        __syncthreads();
#pragma unroll
        for (int i = 0; i < 4; i++) {
            uint4 a = px[t + i * TPB];
            const unsigned b[4] = {a.x, a.y, a.z, a.w};
#pragma unroll
            for (int c = 0; c < 4; c++) {
                unsigned kk = b[c] & 0x7FFFFFFFu;
                if ((kk >> 10) == pref21)
                    atomicAdd(&hist[kk & 0x3FFu], 1u);
            }
        }
        __syncthreads();
        suffix_select<1024>(hist, k, t, lane, wid, wsum, wtail, &sh_digit, &sh_k);
        const unsigned T = (pref21 << 10) | sh_digit;

        // full exact re-store
#pragma unroll
        for (int i = 0; i < 4; i++) {
            uint4 a = px[t + i * TPB];
            const unsigned b[4] = {a.x, a.y, a.z, a.w};
            unsigned o[4];
#pragma unroll
            for (int c = 0; c < 4; c++) {
                unsigned kk = b[c] & 0x7FFFFFFFu;
                o[c] = (kk < T) ? 0u : b[c];
            }
            po[t + i * TPB] = make_uint4(o[0], o[1], o[2], o[3]);
        }
    }
}

extern "C" void kernel_launch(void* const* d_in, const int* in_sizes, int n_in,
                              void* d_out, int out_size) {
    const float* x = (const float*)d_in[0];
    float* out = (float*)d_out;
    const int rows = in_sizes[0] / ROWLEN;   // 4096
    topk_mask_kernel<<<rows, TPB>>>(x, out);
}

// round 15
// speedup vs baseline: 1.5950x; 1.0599x over previous
#include <cuda_runtime.h>
#include <cstdint>

// TopK-magnitude masking per row. x: (4096, 8192) fp32, K = 819.
// out[r,c] = x[r,c] if |x[r,c]| >= (K-th largest |x| in row r) else 0.
//
// Bracketed exact select (rows ~ N(0,1): the 819th largest |x| lies in
// [1.5, 1.8] with ~9-sigma margins). ONE fused global sweep writes the final
// output for decided elements and keeps register-only bookkeeping (candidate
// bitmask + hi count; no atomics/ballots in the sweep). A block scan assigns
// compaction offsets; candidates (~505/row) are written sparsely via __ffs
// iteration (~1 iter/thread). EXACT 2-pass radix over candidates gives the
// true K-th key; a scattered fixup zeroes bracket losers. CTA-uniform
// fallback to a full 3-pass radix keeps the kernel exact for ANY input.

#define ROWLEN  8192
#define TPB     512
#define KSEL    819u
#define NW      (TPB / 32)     // 16 warps
#define CANDMAX 1024
#define KA      0x3FC00000u    // bits(1.5f)
#define KB      0x3FE66666u    // bits(1.8f)

// Suffix-scan + digit select over h[NB] (B = NB/TPB bins per thread).
// Outputs *sh_digit, *sh_k (rank within digit). Ends with __syncthreads.
template <int NB>
__device__ __forceinline__ void suffix_select(
    const unsigned* __restrict__ h, unsigned k,
    int t, int lane, int wid,
    unsigned* wsum, unsigned* wtail,
    unsigned* sh_digit, unsigned* sh_k)
{
    constexpr int B = NB / TPB;
    const int base = t * B;
    unsigned loc[B];
    unsigned s = 0u;
#pragma unroll
    for (int j = B - 1; j >= 0; j--) { s += h[base + j]; loc[j] = s; }
    unsigned p = s;                        // warp suffix scan of chunk totals
#pragma unroll
    for (int off = 1; off < 32; off <<= 1) {
        unsigned n = __shfl_down_sync(0xFFFFFFFFu, p, off);
        if (lane < 32 - off) p += n;
    }
    if (lane == 0) wsum[wid] = p;
    __syncthreads();
    if (t < NW) {
        unsigned q = wsum[t];
        unsigned r = q;
#pragma unroll
        for (int off = 1; off < NW; off <<= 1) {
            unsigned n = __shfl_down_sync(0x0000FFFFu, r, off);
            if (t < NW - off) r += n;
        }
        wtail[t] = r - q;                  // total of warps AFTER warp t
    }
    __syncthreads();
    unsigned beyond = (p - s) + wtail[wid];
#pragma unroll
    for (int j = 0; j < B; j++) {
        unsigned incl = loc[j] + beyond;                          // count(>=d)
        unsigned cnt  = loc[j] - ((j < B - 1) ? loc[j + 1] : 0u); // hist[d]
        unsigned gt   = incl - cnt;                               // count(>d)
        if (incl >= k && gt < k) { *sh_digit = (unsigned)(base + j); *sh_k = k - gt; }
    }
    __syncthreads();
}

__global__ __launch_bounds__(TPB, 4)
void topk_mask_kernel(const float* __restrict__ x, float* __restrict__ out) {
    __shared__ unsigned       hist[2048];        // 8 KB
    __shared__ unsigned       ck[CANDMAX];       // 4 KB  candidate keys
    __shared__ unsigned short cpos[CANDMAX];     // 2 KB  candidate positions
    __shared__ unsigned       wsum[NW], wtail[NW], whi[NW], wbase[NW];
    __shared__ unsigned       sh_digit, sh_k, sh_cc, sh_hi;

    const int t    = threadIdx.x;
    const int lane = t & 31;
    const int wid  = t >> 5;
    const size_t row_off = (size_t)blockIdx.x * ROWLEN;
    const unsigned* __restrict__ pxs  = reinterpret_cast<const unsigned*>(x + row_off);
    const uint4*    __restrict__ px   = reinterpret_cast<const uint4*>(x + row_off);
    uint4*          __restrict__ po   = reinterpret_cast<uint4*>(out + row_off);
    float*          __restrict__ pout = out + row_off;

    // ---- zero pass-A histogram ----
    reinterpret_cast<uint4*>(hist)[t] = make_uint4(0u, 0u, 0u, 0u);
    __syncthreads();

    // ---- fused sweep: load -> final store + register-only bookkeeping ----
    unsigned cmask = 0u;     // bit idx=i*4+c set if element in [1.5, 1.8]
    unsigned myhi  = 0u;     // count of |x| > 1.8
#pragma unroll
    for (int i = 0; i < 4; i++) {
        uint4 a = px[t + i * TPB];
        const unsigned b[4] = {a.x, a.y, a.z, a.w};
        unsigned o[4];
#pragma unroll
        for (int c = 0; c < 4; c++) {
            unsigned key = b[c] & 0x7FFFFFFFu;
            bool lo = (key < KA);
            bool hi = (key > KB);
            o[c] = lo ? 0u : b[c];            // decided or provisional keep
            myhi += hi;
            if (!lo && !hi) cmask |= 1u << (i * 4 + c);
        }
        po[t + i * TPB] = make_uint4(o[0], o[1], o[2], o[3]);
    }
    const unsigned cnt = (unsigned)__popc(cmask);

    // ---- block scan of candidate counts + block reduce of hi counts ----
    unsigned inc = cnt;                     // warp inclusive scan
#pragma unroll
    for (int off = 1; off < 32; off <<= 1) {
        unsigned n = __shfl_up_sync(0xFFFFFFFFu, inc, off);
        if (lane >= off) inc += n;
    }
    {
        unsigned h = myhi;                  // warp reduce
#pragma unroll
        for (int off = 16; off >= 1; off >>= 1)
            h += __shfl_down_sync(0xFFFFFFFFu, h, off);
        if (lane == 31) wsum[wid] = inc;
        if (lane == 0)  whi[wid]  = h;
    }
    __syncthreads();
    if (t < NW) {
        unsigned q = wsum[t];
        unsigned e = q;                     // inclusive scan over 16 warps
#pragma unroll
        for (int off = 1; off < NW; off <<= 1) {
            unsigned n = __shfl_up_sync(0x0000FFFFu, e, off);
            if (t >= off) e += n;
        }
        wbase[t] = e - q;                   // exclusive base for warp t
        if (t == NW - 1) sh_cc = e;         // total candidates
        unsigned hh = whi[t];
#pragma unroll
        for (int off = NW / 2; off >= 1; off >>= 1)
            hh += __shfl_down_sync(0x0000FFFFu, hh, off);
        if (t == 0) sh_hi = hh;
    }
    __syncthreads();

    const unsigned HI = sh_hi;
    const unsigned CC = sh_cc;

    // ---- sparse candidate write: ~1 iteration per thread ----
    if (CC <= CANDMAX) {
        unsigned off = wbase[wid] + inc - cnt;   // exclusive global offset
        unsigned m = cmask;
        while (m) {
            const int idx = __ffs(m) - 1;
            m &= m - 1u;
            const int pos = 4 * t + (idx & 3) + 2048 * (idx >> 2);
            ck[off]   = pxs[pos] & 0x7FFFFFFFu;  // L1/L2-hot re-read
            cpos[off] = (unsigned short)pos;
            off++;
        }
    }
    __syncthreads();

    const bool fast = (HI < KSEL) && (CC <= CANDMAX) && (HI + CC >= KSEL);

    if (fast) {
        unsigned k = KSEL - HI;            // rank among candidates

        // ---- pass A: mantissa bits [11,22), 2048 bins, ~1 cand/thread ----
        for (unsigned j = t; j < CC; j += TPB)
            atomicAdd(&hist[(ck[j] >> 11) & 0x7FFu], 1u);
        __syncthreads();
        suffix_select<2048>(hist, k, t, lane, wid, wsum, wtail, &sh_digit, &sh_k);
        const unsigned dA = sh_digit; k = sh_k;

        // ---- pass B: mantissa bits [0,11), 2048 bins ----
        reinterpret_cast<uint4*>(hist)[t] = make_uint4(0u, 0u, 0u, 0u);
        __syncthreads();
        for (unsigned j = t; j < CC; j += TPB) {
            unsigned kk = ck[j];
            if (((kk >> 11) & 0x7FFu) == dA)
                atomicAdd(&hist[kk & 0x7FFu], 1u);
        }
        __syncthreads();
        suffix_select<2048>(hist, k, t, lane, wid, wsum, wtail, &sh_digit, &sh_k);

        // all candidates share the top 10 bits (exponent of [1,2)): exact T
        const unsigned T = (KA & 0xFFC00000u) | (dA << 11) | sh_digit;

        // ---- fixup: zero bracket losers (scattered ~250 stores/row) ----
        for (unsigned j = t; j < CC; j += TPB)
            if (ck[j] < T)
                pout[cpos[j]] = 0.0f;
    } else {
        // ======== exact fallback: full 3-pass radix (11+10+10) from x ======
        unsigned k = KSEL;

        reinterpret_cast<uint4*>(hist)[t] = make_uint4(0u, 0u, 0u, 0u);
        __syncthreads();
#pragma unroll
        for (int i = 0; i < 4; i++) {
            uint4 a = px[t + i * TPB];
            const unsigned b[4] = {a.x, a.y, a.z, a.w};
#pragma unroll
            for (int c = 0; c < 4; c++)
                atomicAdd(&hist[(b[c] & 0x7FFFFFFFu) >> 20], 1u);
        }
        __syncthreads();
        suffix_select<2048>(hist, k, t, lane, wid, wsum, wtail, &sh_digit, &sh_k);
        const unsigned d1 = sh_digit; k = sh_k;

        reinterpret_cast<uint4*>(hist)[t] = make_uint4(0u, 0u, 0u, 0u);
        __syncthreads();
#pragma unroll
        for (int i = 0; i < 4; i++) {
            uint4 a = px[t + i * TPB];
            const unsigned b[4] = {a.x, a.y, a.z, a.w};
#pragma unroll
            for (int c = 0; c < 4; c++) {
                unsigned kk = b[c] & 0x7FFFFFFFu;
                if ((kk >> 20) == d1)
                    atomicAdd(&hist[(kk >> 10) & 0x3FFu], 1u);
            }
        }
        __syncthreads();
        suffix_select<1024>(hist, k, t, lane, wid, wsum, wtail, &sh_digit, &sh_k);
        const unsigned d2 = sh_digit; k = sh_k;
        const unsigned pref21 = (d1 << 10) | d2;

        reinterpret_cast<uint4*>(hist)[t] = make_uint4(0u, 0u, 0u, 0u);
        __syncthreads();
#pragma unroll
        for (int i = 0; i < 4; i++) {
            uint4 a = px[t + i * TPB];
            const unsigned b[4] = {a.x, a.y, a.z, a.w};
#pragma unroll
            for (int c = 0; c < 4; c++) {
                unsigned kk = b[c] & 0x7FFFFFFFu;
                if ((kk >> 10) == pref21)
                    atomicAdd(&hist[kk & 0x3FFu], 1u);
            }
        }
        __syncthreads();
        suffix_select<1024>(hist, k, t, lane, wid, wsum, wtail, &sh_digit, &sh_k);
        const unsigned T = (pref21 << 10) | sh_digit;

        // full exact re-store
#pragma unroll
        for (int i = 0; i < 4; i++) {
            uint4 a = px[t + i * TPB];
            const unsigned b[4] = {a.x, a.y, a.z, a.w};
            unsigned o[4];
#pragma unroll
            for (int c = 0; c < 4; c++) {
                unsigned kk = b[c] & 0x7FFFFFFFu;
                o[c] = (kk < T) ? 0u : b[c];
            }
            po[t + i * TPB] = make_uint4(o[0], o[1], o[2], o[3]);
        }
    }
}

extern "C" void kernel_launch(void* const* d_in, const int* in_sizes, int n_in,
                              void* d_out, int out_size) {
    const float* x = (const float*)d_in[0];
    float* out = (float*)d_out;
    const int rows = in_sizes[0] / ROWLEN;   // 4096
    topk_mask_kernel<<<rows, TPB>>>(x, out);
}